// round 15
// baseline (speedup 1.0000x reference)
#include <cuda_runtime.h>

#define THREADS 512
#define ROWS    64

// Prep block layout (floats) — identical in gPrep and shared memory:
#define OFF_WT   0        // 64 x 64   Wt[k][i]
#define OFF_E    4096     // 64 x 128  E[k][j] = [Gt | M]
#define OFF_B    12288
#define OFF_WY   12352
#define OFF_wy   12416
#define OFF_wlt  12480
#define OFF_wys  12544
#define OFF_MISC 12608    // [0]=wl[64]
#define PREP_FLOATS 12624

// shared-only extras
#define OFF_RED  12624    // 16 warps x 2 = 32
#define OFF_PART 12656    // 7 partner q's x 4 vals x 64 rows = 1792
#define OFF_FLAG 14448
#define OFF_Z    14452    // 64 rows x 129: x at [0..63], s at [64..127] (odd stride)
#define OFF_SY   22708    // 64 y values
#define SMEM_FLOATS 22772
#define SMEM_BYTES  (SMEM_FLOATS * 4)

// ---- persistent device scratch ----
__device__ float        gPrep[PREP_FLOATS];
__device__ float        gPartI[512];
__device__ float        gPartN[512];
__device__ unsigned int gCount = 0;

__device__ __forceinline__ int pair_off(int i) {
    return 129 + i * (2 * 129 - i - 1) / 2;
}
__device__ __forceinline__ unsigned long long packpair(float a, float b) {
    unsigned long long r;
    asm("mov.b64 %0, {%1, %2};" : "=l"(r) : "f"(a), "f"(b));
    return r;
}
__device__ __forceinline__ void unpack2(unsigned long long v, float& a, float& b) {
    asm("mov.b64 {%0, %1}, %2;" : "=f"(a), "=f"(b) : "l"(v));
}
#define FMA2(acc, a, b) asm("fma.rn.f32x2 %0, %1, %2, %0;" : "+l"(acc) : "l"(a), "l"(b))

__device__ __forceinline__ float red2(unsigned long long v) {
    float a, b;
    unpack2(v, a, b);
    return a + b;
}

__device__ __forceinline__ float tanh_fast(float w) {
    float e, r;
    asm("ex2.approx.f32 %0, %1;" : "=f"(e) : "f"(w * 2.885390081777927f));
    asm("rcp.approx.f32 %0, %1;" : "=f"(r) : "f"(e + 1.0f));
    return fmaf(-2.0f, r, 1.0f);
}

// ---------------------------------------------------------------------------
__global__ void prep_kernel(const float* __restrict__ tw,
                            const float* __restrict__ tb,
                            const float* __restrict__ mw) {
    int tid = blockIdx.x * blockDim.x + threadIdx.x;
    if (tid >= PREP_FLOATS) return;
    float v = 0.0f;
    if (tid < 4096) {                       // Wt[k][i]
        int k = tid >> 6, i = tid & 63;
        v = tw[k * 65 + i];
    } else if (tid < 12288) {               // E[k][j] = [Gt | M]
        int idx = tid - 4096;
        int k = idx >> 7, j = idx & 127;
        if (j < 64) {                       // Gt[k][j]: pair (x_j, t_k)
            v = mw[pair_off(j) + 64 + k - j];
        } else {                            // M[k][l]
            int l = j - 64;
            if (k != l) {
                int a = k < l ? k : l;
                int b = k < l ? l : k;
                v = 0.5f * mw[pair_off(65 + a) + b - a - 1];
            }
        }
    } else if (tid < 12352) {
        v = tb[tid - 12288];
    } else if (tid < 12416) {
        int k = tid - 12352;
        v = tw[k * 65 + 64];
    } else if (tid < 12480) {
        int i = tid - 12416;
        v = mw[pair_off(i) + 63 - i];
    } else if (tid < 12544) {
        v = mw[65 + (tid - 12480)];
    } else if (tid < 12608) {
        v = mw[pair_off(64) + (tid - 12544)];
    } else if (tid == 12608) {
        v = mw[64];
    }
    gPrep[tid] = v;
    if (tid == 0) gCount = 0;
}

// ---------------------------------------------------------------------------
// 512 threads: warp = (rowhalf, k-eighth). lane = row within half.
// Low register pressure (<=64) -> 2 blocks/SM -> 8 warps/SMSP.
// Phase 1: c = x.Wt (per-k packed acc). Phase 2: gz = d^T E [x|s].
// ---------------------------------------------------------------------------
__global__ void __launch_bounds__(THREADS, 2)
fused_kernel(const float* __restrict__ inps,
             float* __restrict__ out,
             int Bn) {
    extern __shared__ float sm[];
    const int t    = threadIdx.x;
    const int lane = t & 31;
    const int w    = t >> 5;          // warp 0..15
    const int q    = w & 7;           // k-eighth (warp-uniform)
    const int kb   = q * 8;
    const int r    = ((w >> 3) << 5) + lane;   // row 0..63
    const int row0 = blockIdx.x * ROWS;

    // coalesced weight copy
    {
        const float4* src = reinterpret_cast<const float4*>(gPrep);
        float4* dst = reinterpret_cast<float4*>(sm);
        for (int idx = t; idx < PREP_FLOATS / 4; idx += THREADS)
            dst[idx] = src[idx];
    }
    // input stage: x -> z[0..63], y -> sy
    {
        const float* gsrc = inps + (long)row0 * 65;
        for (int idx = t; idx < ROWS * 65; idx += THREADS) {
            int rr = idx / 65, cc = idx - rr * 65;
            float v = gsrc[idx];
            if (cc < 64) sm[OFF_Z + rr * 129 + cc] = v;
            else         sm[OFF_SY + rr] = v;
        }
    }
    __syncthreads();

    float* zr = sm + OFF_Z + r * 129;   // x at [0..63], s at [64..127]
    const float yv = sm[OFF_SY + r];

    // x . wy over this warp's 8 i's
    float xw = 0.0f;
#pragma unroll
    for (int j = 0; j < 8; j++)
        xw = fmaf(zr[kb + j], sm[OFF_wy + kb + j], xw);

    // ---- Phase 1: c_k = x . Wt[k][:] over this warp's 8 k's ----
    unsigned long long cacc[8];
#pragma unroll
    for (int kk = 0; kk < 8; kk++) cacc[kk] = 0ULL;

#pragma unroll
    for (int qt = 0; qt < 4; qt++) {
        unsigned long long xa[8];
#pragma unroll
        for (int j = 0; j < 8; j++)
            xa[j] = packpair(zr[qt * 16 + 2 * j], zr[qt * 16 + 2 * j + 1]);
#pragma unroll
        for (int kk = 0; kk < 8; kk++) {
            const ulonglong2* pW =
                reinterpret_cast<const ulonglong2*>(sm + OFF_WT + (kb + kk) * 64 + qt * 16);
            ulonglong2 W0 = pW[0], W1 = pW[1], W2 = pW[2], W3 = pW[3];
            FMA2(cacc[kk], xa[0], W0.x); FMA2(cacc[kk], xa[1], W0.y);
            FMA2(cacc[kk], xa[2], W1.x); FMA2(cacc[kk], xa[3], W1.y);
            FMA2(cacc[kk], xa[4], W2.x); FMA2(cacc[kk], xa[5], W2.y);
            FMA2(cacc[kk], xa[6], W3.x); FMA2(cacc[kk], xa[7], W3.y);
        }
    }

    // ---- epilogue: tanh, d (regs) / s (smem), penalties, small dots ----
    float d[8];
    float dw = 0.0f, sw = 0.0f, accI = 0.0f, accN = 0.0f;
#pragma unroll
    for (int kk = 0; kk < 8; kk++) {
        int k = kb + kk;
        float cv = red2(cacc[kk]) + sm[OFF_B + k];
        float hv = yv * sm[OFF_WY + k];
        float w1 = cv + hv, w2 = cv - hv;
        float t1 = tanh_fast(w1), t2 = tanh_fast(w2);
        float dk = t1 - t2, sk = t1 + t2;
        d[kk]      = dk;
        zr[64 + k] = sk;
        dw = fmaf(dk, sm[OFF_wlt + k], dw);
        sw = fmaf(sk, sm[OFF_wys + k], sw);
        float e1 = fmaf(-t1, t1, 1.0f), e2 = fmaf(-t2, t2, 1.0f);
        accI = fmaf(e1, e1, accI);
        accI = fmaf(e2, e2, accI);
        float nt = fmaf(t2, w2, -(t1 * w1));
        accN = fmaf(nt, nt, accN);
    }

    __syncthreads();   // all s written

    // ---- Phase 2: gz = sum_k d_k * (E z)_k,  z = [x|s] contiguous 128 ----
    unsigned long long macc[8];
#pragma unroll
    for (int kk = 0; kk < 8; kk++) macc[kk] = 0ULL;

#pragma unroll
    for (int ct = 0; ct < 8; ct++) {
        unsigned long long za[8];
#pragma unroll
        for (int j = 0; j < 8; j++)
            za[j] = packpair(zr[ct * 16 + 2 * j], zr[ct * 16 + 2 * j + 1]);
#pragma unroll
        for (int kk = 0; kk < 8; kk++) {
            const ulonglong2* pE =
                reinterpret_cast<const ulonglong2*>(sm + OFF_E + (kb + kk) * 128 + ct * 16);
            ulonglong2 E0 = pE[0], E1 = pE[1], E2 = pE[2], E3 = pE[3];
            FMA2(macc[kk], za[0], E0.x); FMA2(macc[kk], za[1], E0.y);
            FMA2(macc[kk], za[2], E1.x); FMA2(macc[kk], za[3], E1.y);
            FMA2(macc[kk], za[4], E2.x); FMA2(macc[kk], za[5], E2.y);
            FMA2(macc[kk], za[6], E3.x); FMA2(macc[kk], za[7], E3.y);
        }
    }
    float gz = 0.0f;
#pragma unroll
    for (int kk = 0; kk < 8; kk++)
        gz = fmaf(d[kk], red2(macc[kk]), gz);

    // ---- combine the 8 k-eighth warps per row ----
    if (q != 0) {
        int p = OFF_PART + (q - 1) * 256;
        sm[p + r]       = gz;
        sm[p + 64 + r]  = dw;
        sm[p + 128 + r] = sw;
        sm[p + 192 + r] = xw;
    }
    __syncthreads();
    if (q == 0) {
        float gzT = gz, dwT = dw, swT = sw, xwT = xw;
#pragma unroll
        for (int p = 0; p < 7; p++) {
            int b = OFF_PART + p * 256;
            gzT += sm[b + r];
            dwT += sm[b + 64 + r];
            swT += sm[b + 128 + r];
            xwT += sm[b + 192 + r];
        }
        float wl64 = sm[OFF_MISC];
        out[row0 + r] = 1.0f + 2.0f * yv * wl64 + dwT + 2.0f * yv * xwT + yv * swT + gzT;
    }

    // ---- penalty reduction ----
#pragma unroll
    for (int off = 16; off > 0; off >>= 1) {
        accI += __shfl_xor_sync(0xffffffffu, accI, off);
        accN += __shfl_xor_sync(0xffffffffu, accN, off);
    }
    if (lane == 0) {
        sm[OFF_RED + w]      = accI;
        sm[OFF_RED + 16 + w] = accN;
    }
    __syncthreads();
    if (t == 0) {
        float pI = 0.0f, pN = 0.0f;
#pragma unroll
        for (int ww = 0; ww < 16; ww++) { pI += sm[OFF_RED + ww]; pN += sm[OFF_RED + 16 + ww]; }
        gPartI[blockIdx.x] = pI;
        gPartN[blockIdx.x] = pN;
        __threadfence();
        unsigned int tk = atomicAdd(&gCount, 1u);
        sm[OFF_FLAG] = (tk == gridDim.x - 1) ? 1.0f : 0.0f;
    }
    __syncthreads();

    if (sm[OFF_FLAG] != 0.0f && t < 32) {
        __threadfence();
        double sI = 0.0, sN = 0.0;
        for (int i = t; i < (int)gridDim.x; i += 32) {
            sI += (double)gPartI[i];
            sN += (double)gPartN[i];
        }
#pragma unroll
        for (int off = 16; off > 0; off >>= 1) {
            sI += __shfl_xor_sync(0xffffffffu, sI, off);
            sN += __shfl_xor_sync(0xffffffffu, sN, off);
        }
        if (t == 0) {
            out[Bn]     = (float)(sI * (1.0 / 300.0));
            out[Bn + 1] = (float)sN;
            gCount = 0;   // reset for next graph replay
        }
    }
}

extern "C" void kernel_launch(void* const* d_in, const int* in_sizes, int n_in,
                              void* d_out, int out_size) {
    const float* inps = (const float*)d_in[0];
    const float* tw   = (const float*)d_in[1];
    const float* tb   = (const float*)d_in[2];
    const float* mw   = (const float*)d_in[3];
    float* out = (float*)d_out;

    int Bn = in_sizes[0] / 65;

    cudaFuncSetAttribute(fused_kernel,
                         cudaFuncAttributeMaxDynamicSharedMemorySize, SMEM_BYTES);

    prep_kernel<<<(PREP_FLOATS + 255) / 256, 256>>>(tw, tb, mw);
    fused_kernel<<<Bn / ROWS, THREADS, SMEM_BYTES>>>(inps, out, Bn);
}

// round 16
// speedup vs baseline: 1.2015x; 1.2015x over previous
#include <cuda_runtime.h>

#define THREADS 512
#define ROWS    128
#define ZSTR    130

// Prep block layout (floats) — identical in gPrep and shared memory:
#define OFF_WT   0        // 64 x 64   Wt[k][i]
#define OFF_E    4096     // 64 x 128  E[k][j] = [Gt | M]
#define OFF_B    12288
#define OFF_WY   12352
#define OFF_wy   12416
#define OFF_wlt  12480
#define OFF_wys  12544
#define OFF_MISC 12608    // [0]=wl[64]
#define PREP_FLOATS 12624

// shared-only extras
#define OFF_RED  12624    // 16 warps x 2 = 32
#define OFF_PART 12656    // 15 partner q's x 128 rows = 1920
#define OFF_FLAG 14576
#define OFF_SY   14580    // 128 y values
#define OFF_Z    14708    // 128 rows x 130: x[0..63], s[64..127]; even 8B-aligned stride
#define SMEM_FLOATS (OFF_Z + ROWS * ZSTR)
#define SMEM_BYTES  (SMEM_FLOATS * 4)

// ---- persistent device scratch ----
__device__ float        gPrep[PREP_FLOATS];
__device__ float        gPartI[512];
__device__ float        gPartN[512];
__device__ unsigned int gCount = 0;

__device__ __forceinline__ int pair_off(int i) {
    return 129 + i * (2 * 129 - i - 1) / 2;
}
__device__ __forceinline__ void unpack2(unsigned long long v, float& a, float& b) {
    asm("mov.b64 {%0, %1}, %2;" : "=f"(a), "=f"(b) : "l"(v));
}
#define FMA2(acc, a, b) asm("fma.rn.f32x2 %0, %1, %2, %0;" : "+l"(acc) : "l"(a), "l"(b))

__device__ __forceinline__ unsigned long long lds64(const float* p) {
    return *reinterpret_cast<const unsigned long long*>(p);
}
__device__ __forceinline__ float red2(unsigned long long v) {
    float a, b;
    unpack2(v, a, b);
    return a + b;
}
__device__ __forceinline__ float tanh_fast(float w) {
    float e, r;
    asm("ex2.approx.f32 %0, %1;" : "=f"(e) : "f"(w * 2.885390081777927f));
    asm("rcp.approx.f32 %0, %1;" : "=f"(r) : "f"(e + 1.0f));
    return fmaf(-2.0f, r, 1.0f);
}

// ---------------------------------------------------------------------------
__global__ void prep_kernel(const float* __restrict__ tw,
                            const float* __restrict__ tb,
                            const float* __restrict__ mw) {
    int tid = blockIdx.x * blockDim.x + threadIdx.x;
    if (tid >= PREP_FLOATS) return;
    float v = 0.0f;
    if (tid < 4096) {                       // Wt[k][i]
        int k = tid >> 6, i = tid & 63;
        v = tw[k * 65 + i];
    } else if (tid < 12288) {               // E[k][j] = [Gt | M]
        int idx = tid - 4096;
        int k = idx >> 7, j = idx & 127;
        if (j < 64) {
            v = mw[pair_off(j) + 64 + k - j];
        } else {
            int l = j - 64;
            if (k != l) {
                int a = k < l ? k : l;
                int b = k < l ? l : k;
                v = 0.5f * mw[pair_off(65 + a) + b - a - 1];
            }
        }
    } else if (tid < 12352) {
        v = tb[tid - 12288];
    } else if (tid < 12416) {
        int k = tid - 12352;
        v = tw[k * 65 + 64];
    } else if (tid < 12480) {
        int i = tid - 12416;
        v = mw[pair_off(i) + 63 - i];
    } else if (tid < 12544) {
        v = mw[65 + (tid - 12480)];
    } else if (tid < 12608) {
        v = mw[pair_off(64) + (tid - 12544)];
    } else if (tid == 12608) {
        v = mw[64];
    }
    gPrep[tid] = v;
    if (tid == 0) gCount = 0;
}

// ---------------------------------------------------------------------------
// 512 threads, 128 rows/block. warp = k-sixteenth (4 k's, warp-uniform
// weight reads). lane = 4 rows {lane, +32, +64, +96}: each 16B weight load
// feeds 8 FMA2 (4 rows x f32x2). z stride 130 -> true LDS.64 pack loads.
// ---------------------------------------------------------------------------
__global__ void __launch_bounds__(THREADS, 1)
fused_kernel(const float* __restrict__ inps,
             float* __restrict__ out,
             int Bn) {
    extern __shared__ float sm[];
    const int t    = threadIdx.x;
    const int lane = t & 31;
    const int q    = t >> 5;          // warp = k-sixteenth, 0..15
    const int kb   = q * 4;
    const int row0 = blockIdx.x * ROWS;

    // coalesced weight copy
    {
        const float4* src = reinterpret_cast<const float4*>(gPrep);
        float4* dst = reinterpret_cast<float4*>(sm);
        for (int idx = t; idx < PREP_FLOATS / 4; idx += THREADS)
            dst[idx] = src[idx];
    }
    // input stage: x -> z[0..63] (stride 130), y -> sy
    {
        const float* gsrc = inps + (long)row0 * 65;
        for (int idx = t; idx < ROWS * 65; idx += THREADS) {
            int rr = idx / 65, cc = idx - rr * 65;
            float v = gsrc[idx];
            if (cc < 64) sm[OFF_Z + rr * ZSTR + cc] = v;
            else         sm[OFF_SY + rr] = v;
        }
    }
    __syncthreads();

    const float* Z0 = sm + OFF_Z + lane * ZSTR;          // row lane
    const float* Z1 = Z0 + 32 * ZSTR;
    const float* Z2 = Z0 + 64 * ZSTR;
    const float* Z3 = Z0 + 96 * ZSTR;
    float yv[4];
    yv[0] = sm[OFF_SY + lane];
    yv[1] = sm[OFF_SY + lane + 32];
    yv[2] = sm[OFF_SY + lane + 64];
    yv[3] = sm[OFF_SY + lane + 96];

    // x . wy over this warp's 4 i's
    float xw[4] = {0.0f, 0.0f, 0.0f, 0.0f};
#pragma unroll
    for (int j = 0; j < 4; j++) {
        float w = sm[OFF_wy + kb + j];
        xw[0] = fmaf(Z0[kb + j], w, xw[0]);
        xw[1] = fmaf(Z1[kb + j], w, xw[1]);
        xw[2] = fmaf(Z2[kb + j], w, xw[2]);
        xw[3] = fmaf(Z3[kb + j], w, xw[3]);
    }

    // ---- Phase 1: c[k][row] = x_row . Wt[k][:] ----
    unsigned long long cacc[4][4];    // [kk][row]
#pragma unroll
    for (int kk = 0; kk < 4; kk++)
#pragma unroll
        for (int j = 0; j < 4; j++) cacc[kk][j] = 0ULL;

#pragma unroll
    for (int ch = 0; ch < 8; ch++) {                     // 8 cols per chunk
        unsigned long long xp[4][4];                     // [row][pack]
#pragma unroll
        for (int p = 0; p < 4; p++) {
            xp[0][p] = lds64(Z0 + ch * 8 + 2 * p);
            xp[1][p] = lds64(Z1 + ch * 8 + 2 * p);
            xp[2][p] = lds64(Z2 + ch * 8 + 2 * p);
            xp[3][p] = lds64(Z3 + ch * 8 + 2 * p);
        }
#pragma unroll
        for (int kk = 0; kk < 4; kk++) {
            const ulonglong2* pW =
                reinterpret_cast<const ulonglong2*>(sm + OFF_WT + (kb + kk) * 64 + ch * 8);
            ulonglong2 W0 = pW[0], W1 = pW[1];
#pragma unroll
            for (int j = 0; j < 4; j++) {
                FMA2(cacc[kk][j], xp[j][0], W0.x);
                FMA2(cacc[kk][j], xp[j][1], W0.y);
                FMA2(cacc[kk][j], xp[j][2], W1.x);
                FMA2(cacc[kk][j], xp[j][3], W1.y);
            }
        }
    }

    // ---- epilogue: tanh, d (regs) / s (smem), penalties, small dots ----
    float d[4][4];
    float dw[4] = {0, 0, 0, 0}, sw[4] = {0, 0, 0, 0};
    float accI = 0.0f, accN = 0.0f;
#pragma unroll
    for (int kk = 0; kk < 4; kk++) {
        int k = kb + kk;
        float bk  = sm[OFF_B + k];
        float wyk = sm[OFF_WY + k];
        float wlt = sm[OFF_wlt + k];
        float wys = sm[OFF_wys + k];
#pragma unroll
        for (int j = 0; j < 4; j++) {
            float cv = red2(cacc[kk][j]) + bk;
            float hv = yv[j] * wyk;
            float w1 = cv + hv, w2 = cv - hv;
            float t1 = tanh_fast(w1), t2 = tanh_fast(w2);
            float dk = t1 - t2, sk = t1 + t2;
            d[kk][j] = dk;
            sm[OFF_Z + (lane + 32 * j) * ZSTR + 64 + k] = sk;
            dw[j] = fmaf(dk, wlt, dw[j]);
            sw[j] = fmaf(sk, wys, sw[j]);
            float e1 = fmaf(-t1, t1, 1.0f), e2 = fmaf(-t2, t2, 1.0f);
            accI = fmaf(e1, e1, accI);
            accI = fmaf(e2, e2, accI);
            float nt = fmaf(t2, w2, -(t1 * w1));
            accN = fmaf(nt, nt, accN);
        }
    }

    __syncthreads();   // all s written

    // ---- Phase 2: gz[row] = sum_k d_k * (E z)_k,  z = [x|s] 128 cols ----
    unsigned long long macc[4][4];
#pragma unroll
    for (int kk = 0; kk < 4; kk++)
#pragma unroll
        for (int j = 0; j < 4; j++) macc[kk][j] = 0ULL;

#pragma unroll
    for (int ch = 0; ch < 16; ch++) {
        unsigned long long zp[4][4];
#pragma unroll
        for (int p = 0; p < 4; p++) {
            zp[0][p] = lds64(Z0 + ch * 8 + 2 * p);
            zp[1][p] = lds64(Z1 + ch * 8 + 2 * p);
            zp[2][p] = lds64(Z2 + ch * 8 + 2 * p);
            zp[3][p] = lds64(Z3 + ch * 8 + 2 * p);
        }
#pragma unroll
        for (int kk = 0; kk < 4; kk++) {
            const ulonglong2* pE =
                reinterpret_cast<const ulonglong2*>(sm + OFF_E + (kb + kk) * 128 + ch * 8);
            ulonglong2 E0 = pE[0], E1 = pE[1];
#pragma unroll
            for (int j = 0; j < 4; j++) {
                FMA2(macc[kk][j], zp[j][0], E0.x);
                FMA2(macc[kk][j], zp[j][1], E0.y);
                FMA2(macc[kk][j], zp[j][2], E1.x);
                FMA2(macc[kk][j], zp[j][3], E1.y);
            }
        }
    }

    // per-row combined partial: dw + y*(2*xw + sw) + gz
    float part[4];
#pragma unroll
    for (int j = 0; j < 4; j++) {
        float gz = 0.0f;
#pragma unroll
        for (int kk = 0; kk < 4; kk++)
            gz = fmaf(d[kk][j], red2(macc[kk][j]), gz);
        part[j] = dw[j] + yv[j] * fmaf(2.0f, xw[j], sw[j]) + gz;
    }

    // ---- combine the 16 k-sixteenth warps per row ----
    if (q != 0) {
        int p = OFF_PART + (q - 1) * 128;
#pragma unroll
        for (int j = 0; j < 4; j++)
            sm[p + lane + 32 * j] = part[j];
    }
    __syncthreads();
    if (q == 0) {
        float wl64 = sm[OFF_MISC];
#pragma unroll
        for (int j = 0; j < 4; j++) {
            float tot = part[j];
#pragma unroll
            for (int p = 0; p < 15; p++)
                tot += sm[OFF_PART + p * 128 + lane + 32 * j];
            out[row0 + lane + 32 * j] = 1.0f + 2.0f * yv[j] * wl64 + tot;
        }
    }

    // ---- penalty reduction ----
#pragma unroll
    for (int off = 16; off > 0; off >>= 1) {
        accI += __shfl_xor_sync(0xffffffffu, accI, off);
        accN += __shfl_xor_sync(0xffffffffu, accN, off);
    }
    if (lane == 0) {
        sm[OFF_RED + q]      = accI;
        sm[OFF_RED + 16 + q] = accN;
    }
    __syncthreads();
    if (t == 0) {
        float pI = 0.0f, pN = 0.0f;
#pragma unroll
        for (int ww = 0; ww < 16; ww++) { pI += sm[OFF_RED + ww]; pN += sm[OFF_RED + 16 + ww]; }
        gPartI[blockIdx.x] = pI;
        gPartN[blockIdx.x] = pN;
        __threadfence();
        unsigned int tk = atomicAdd(&gCount, 1u);
        sm[OFF_FLAG] = (tk == gridDim.x - 1) ? 1.0f : 0.0f;
    }
    __syncthreads();

    if (sm[OFF_FLAG] != 0.0f && t < 32) {
        __threadfence();
        double sI = 0.0, sN = 0.0;
        for (int i = t; i < (int)gridDim.x; i += 32) {
            sI += (double)gPartI[i];
            sN += (double)gPartN[i];
        }
#pragma unroll
        for (int off = 16; off > 0; off >>= 1) {
            sI += __shfl_xor_sync(0xffffffffu, sI, off);
            sN += __shfl_xor_sync(0xffffffffu, sN, off);
        }
        if (t == 0) {
            out[Bn]     = (float)(sI * (1.0 / 300.0));
            out[Bn + 1] = (float)sN;
            gCount = 0;   // reset for next graph replay
        }
    }
}

extern "C" void kernel_launch(void* const* d_in, const int* in_sizes, int n_in,
                              void* d_out, int out_size) {
    const float* inps = (const float*)d_in[0];
    const float* tw   = (const float*)d_in[1];
    const float* tb   = (const float*)d_in[2];
    const float* mw   = (const float*)d_in[3];
    float* out = (float*)d_out;

    int Bn = in_sizes[0] / 65;

    cudaFuncSetAttribute(fused_kernel,
                         cudaFuncAttributeMaxDynamicSharedMemorySize, SMEM_BYTES);

    prep_kernel<<<(PREP_FLOATS + 255) / 256, 256>>>(tw, tb, mw);
    fused_kernel<<<Bn / ROWS, THREADS, SMEM_BYTES>>>(inps, out, Bn);
}